// round 9
// baseline (speedup 1.0000x reference)
#include <cuda_runtime.h>
#include <cuda_bf16.h>
#include <cstdint>

#define BB 32
#define TT 256
#define DD 512
#define PP 20
#define EPSV 1e-12f

// ---------------- scratch (__device__ globals; no cudaMalloc allowed) ------
__device__ __align__(16) __nv_bfloat16 g_nbn_bf [BB * TT * DD];   // [b][t][d]
__device__ __align__(16) __nv_bfloat16 g_nbnT_bf[BB * DD * TT];   // [b][d][t]
__device__ __align__(16) __nv_bfloat16 g_nanT_bf[BB * DD * TT];   // [b][d][t]
__device__ __align__(16) __nv_bfloat16 g_alphaTb[(size_t)BB * DD * DD]; // [b][e][d]
__device__ float g_invcol[BB * DD];                                // per (b,e)
__device__ __align__(16) float g_hmean[BB * TT * DD];              // [b][t][e]
__device__ __align__(16) float g_W2[PP * DD];                      // W*W

__device__ __forceinline__ uint32_t smem_u32(const void* p) {
    return (uint32_t)__cvta_generic_to_shared(p);
}
// pack two fp32 -> bf16x2 (lo = x, hi = y), round-to-nearest-even
__device__ __forceinline__ uint32_t pack_bf2(float x, float y) {
    uint32_t r;
    asm("cvt.rn.bf16x2.f32 %0, %1, %2;" : "=r"(r) : "f"(y), "f"(x));
    return r;
}

// ---------------------------------------------------------------------------
// Kernel 1: row l2-normalize + transpose, bf16 outputs.
// ---------------------------------------------------------------------------
__global__ void __launch_bounds__(256) k_normT(const float* __restrict__ a,
                                               const float* __restrict__ b) {
    __shared__ float s[16 * 513];
    __shared__ float sinv[16];
    int which = blockIdx.z;
    int bb = blockIdx.y;
    int t0 = blockIdx.x * 16;
    const float* src = (which ? b : a) + ((size_t)bb * TT + t0) * DD;
    int tid = threadIdx.x;

#pragma unroll
    for (int i = 0; i < 8; i++) {
        int idx = tid + i * 256;
        int r = idx >> 7, c4 = idx & 127;
        float4 v = *(const float4*)(src + (size_t)r * DD + c4 * 4);
        float* sr = s + r * 513 + c4 * 4;
        sr[0] = v.x; sr[1] = v.y; sr[2] = v.z; sr[3] = v.w;
    }
    __syncthreads();

    int wid = tid >> 5, lid = tid & 31;
#pragma unroll
    for (int rr = 0; rr < 2; rr++) {
        int r = wid * 2 + rr;
        float ss = 0.f;
#pragma unroll
        for (int j = 0; j < 16; j++) { float v = s[r * 513 + lid + 32 * j]; ss += v * v; }
#pragma unroll
        for (int o = 16; o > 0; o >>= 1) ss += __shfl_xor_sync(0xffffffffu, ss, o);
        if (lid == 0) sinv[r] = rsqrtf(fmaxf(ss, EPSV));
    }
    __syncthreads();

    __nv_bfloat16* dstT = (which ? g_nbnT_bf : g_nanT_bf) + (size_t)bb * DD * TT;
#pragma unroll
    for (int i = 0; i < 8; i++) {
        int idx = tid + i * 256;
        int d = idx >> 2, jq = (idx & 3) * 4;
        float o0 = s[(jq + 0) * 513 + d] * sinv[jq + 0];
        float o1 = s[(jq + 1) * 513 + d] * sinv[jq + 1];
        float o2 = s[(jq + 2) * 513 + d] * sinv[jq + 2];
        float o3 = s[(jq + 3) * 513 + d] * sinv[jq + 3];
        uint2 u = make_uint2(pack_bf2(o0, o1), pack_bf2(o2, o3));
        *(uint2*)(dstT + (size_t)d * TT + t0 + jq) = u;
    }
    if (which) {
        __nv_bfloat16* dst = g_nbn_bf + ((size_t)bb * TT + t0) * DD;
#pragma unroll
        for (int i = 0; i < 8; i++) {
            int idx = tid + i * 256;
            int r = idx >> 7, c4 = idx & 127;
            float inv = sinv[r];
            float* sr = s + r * 513 + c4 * 4;
            uint2 u = make_uint2(pack_bf2(sr[0] * inv, sr[1] * inv),
                                 pack_bf2(sr[2] * inv, sr[3] * inv));
            *(uint2*)(dst + (size_t)r * DD + c4 * 4) = u;
        }
    }
}

// ---------------------------------------------------------------------------
// bf16 mma.sync GEMM, 3-stage cp.async pipeline, ldmatrix fragment loads.
// CTA tile 128x128, K-chunk 32. Store transposed: C[n*512 + m].
// out_bf16=1: bf16 store, no scale.  out_bf16=0: fp32 store * scale[m].
// ---------------------------------------------------------------------------
__global__ void __launch_bounds__(256, 2) k_gemm_bf16(
    const __nv_bfloat16* __restrict__ Ag, int lda, size_t strideA,
    const __nv_bfloat16* __restrict__ Bg, int ldb, size_t strideB,
    void* __restrict__ Cg, size_t strideC,
    const float* __restrict__ scale, int Ktot, int out_bf16) {
    __shared__ __align__(16) char sm[3 * 16384];  // 48KB

    int b = blockIdx.z;
    int m0 = blockIdx.x * 128, n0 = blockIdx.y * 128;
    const __nv_bfloat16* A  = Ag + (size_t)b * strideA + (size_t)m0 * lda;
    const __nv_bfloat16* Bp = Bg + (size_t)b * strideB + (size_t)n0 * ldb;

    int tid = threadIdx.x, lane = tid & 31, wid = tid >> 5;
    int wm = wid & 1, wn = wid >> 1;
    uint32_t smbase = smem_u32(sm);

    float acc[4][4][4];
#pragma unroll
    for (int i = 0; i < 4; i++)
#pragma unroll
        for (int j = 0; j < 4; j++)
#pragma unroll
            for (int k = 0; k < 4; k++) acc[i][j][k] = 0.f;

    int nkt = Ktot / 32;

    auto issue_chunk = [&](int kt) {
        uint32_t base = smbase + (uint32_t)(kt % 3) * 16384u;
        int k0 = kt * 32;
#pragma unroll
        for (int i = 0; i < 2; i++) {
            int idx = tid + i * 256;
            int r = idx >> 2, q = idx & 3;
            uint32_t off = (uint32_t)(r * 64 + ((q ^ ((r >> 1) & 3)) << 4));
            const __nv_bfloat16* srcA = A + (size_t)r * lda + k0 + q * 8;
            asm volatile("cp.async.cg.shared.global [%0], [%1], 16;"
                         :: "r"(base + off), "l"(srcA));
            const __nv_bfloat16* srcB = Bp + (size_t)r * ldb + k0 + q * 8;
            asm volatile("cp.async.cg.shared.global [%0], [%1], 16;"
                         :: "r"(base + 8192u + off), "l"(srcB));
        }
        asm volatile("cp.async.commit_group;");
    };

    issue_chunk(0);
    if (nkt > 1) issue_chunk(1);

    for (int kt = 0; kt < nkt; kt++) {
        asm volatile("cp.async.wait_group 1;" ::: "memory");
        __syncthreads();
        if (kt + 2 < nkt) issue_chunk(kt + 2);

        uint32_t baseA = smbase + (uint32_t)(kt % 3) * 16384u;
        uint32_t baseB = baseA + 8192u;

#pragma unroll
        for (int ks = 0; ks < 2; ks++) {
            uint32_t af[4][4], bf[4][2];
#pragma unroll
            for (int mt = 0; mt < 4; mt++) {
                int r = wm * 64 + mt * 16 + (lane & 15);
                int q = ks * 2 + (lane >> 4);
                uint32_t addr = baseA + (uint32_t)(r * 64 + ((q ^ ((r >> 1) & 3)) << 4));
                asm volatile("ldmatrix.sync.aligned.m8n8.x4.shared.b16 {%0,%1,%2,%3}, [%4];"
                             : "=r"(af[mt][0]), "=r"(af[mt][1]),
                               "=r"(af[mt][2]), "=r"(af[mt][3])
                             : "r"(addr));
            }
#pragma unroll
            for (int nt = 0; nt < 4; nt++) {
                int r = wn * 32 + nt * 8 + (lane & 7);
                int q = ks * 2 + ((lane >> 3) & 1);
                uint32_t addr = baseB + (uint32_t)(r * 64 + ((q ^ ((r >> 1) & 3)) << 4));
                asm volatile("ldmatrix.sync.aligned.m8n8.x2.shared.b16 {%0,%1}, [%2];"
                             : "=r"(bf[nt][0]), "=r"(bf[nt][1])
                             : "r"(addr));
            }
#pragma unroll
            for (int mt = 0; mt < 4; mt++)
#pragma unroll
                for (int nt = 0; nt < 4; nt++) {
                    asm volatile(
                        "mma.sync.aligned.m16n8k16.row.col.f32.bf16.bf16.f32 "
                        "{%0,%1,%2,%3}, {%4,%5,%6,%7}, {%8,%9}, {%0,%1,%2,%3};"
                        : "+f"(acc[mt][nt][0]), "+f"(acc[mt][nt][1]),
                          "+f"(acc[mt][nt][2]), "+f"(acc[mt][nt][3])
                        : "r"(af[mt][0]), "r"(af[mt][1]),
                          "r"(af[mt][2]), "r"(af[mt][3]),
                          "r"(bf[nt][0]), "r"(bf[nt][1]));
                }
        }
        __syncthreads();
    }

    // ---- epilogue ----
    if (out_bf16) {
        __nv_bfloat16* Cb = (__nv_bfloat16*)Cg + (size_t)b * strideC;
#pragma unroll
        for (int mt = 0; mt < 4; mt++) {
            int r0 = m0 + wm * 64 + mt * 16 + (lane >> 2);
#pragma unroll
            for (int nt = 0; nt < 4; nt++) {
                int c0 = n0 + wn * 32 + nt * 8 + (lane & 3) * 2;
                Cb[(size_t)c0 * 512 + r0]           = __float2bfloat16(acc[mt][nt][0]);
                Cb[(size_t)(c0 + 1) * 512 + r0]     = __float2bfloat16(acc[mt][nt][1]);
                Cb[(size_t)c0 * 512 + r0 + 8]       = __float2bfloat16(acc[mt][nt][2]);
                Cb[(size_t)(c0 + 1) * 512 + r0 + 8] = __float2bfloat16(acc[mt][nt][3]);
            }
        }
    } else {
        float* Cb = (float*)Cg + (size_t)b * strideC;
        const float* scb = scale + (size_t)b * DD;
#pragma unroll
        for (int mt = 0; mt < 4; mt++) {
            int r0 = m0 + wm * 64 + mt * 16 + (lane >> 2);
            float sc0 = scb[r0];
            float sc1 = scb[r0 + 8];
#pragma unroll
            for (int nt = 0; nt < 4; nt++) {
                int c0 = n0 + wn * 32 + nt * 8 + (lane & 3) * 2;
                Cb[(size_t)c0 * 512 + r0]           = acc[mt][nt][0] * sc0;
                Cb[(size_t)(c0 + 1) * 512 + r0]     = acc[mt][nt][1] * sc0;
                Cb[(size_t)c0 * 512 + r0 + 8]       = acc[mt][nt][2] * sc1;
                Cb[(size_t)(c0 + 1) * 512 + r0 + 8] = acc[mt][nt][3] * sc1;
            }
        }
    }
}

// ---------------------------------------------------------------------------
// Row norms of bf16 alphaT -> invcol. One warp per (b,e) row (512 bf16 = 1KB).
// ---------------------------------------------------------------------------
__global__ void __launch_bounds__(256) k_colnorm() {
    int gw = (blockIdx.x * blockDim.x + threadIdx.x) >> 5;
    int lane = threadIdx.x & 31;
    if (gw >= BB * DD) return;
    const uint4* r4 = (const uint4*)(g_alphaTb + (size_t)gw * DD);
    float ss = 0.f;
#pragma unroll
    for (int i = 0; i < 2; i++) {
        uint4 v = r4[lane + 32 * i];
        uint32_t ws[4] = {v.x, v.y, v.z, v.w};
#pragma unroll
        for (int j = 0; j < 4; j++) {
            float2 f = __bfloat1622float2(*(__nv_bfloat162*)&ws[j]);
            ss += f.x * f.x + f.y * f.y;
        }
    }
#pragma unroll
    for (int o = 16; o > 0; o >>= 1) ss += __shfl_xor_sync(0xffffffffu, ss, o);
    if (lane == 0) g_invcol[gw] = rsqrtf(fmaxf(ss, EPSV));
}

// ---------------------------------------------------------------------------
// W^2 precompute (tiny)
// ---------------------------------------------------------------------------
__global__ void k_w2(const float* __restrict__ W) {
    int i = blockIdx.x * blockDim.x + threadIdx.x;
    if (i < PP * DD) { float w = W[i]; g_W2[i] = w * w; }
}

// ---------------------------------------------------------------------------
// Perspective scores. Block = 8 warps = 8 rows; W^2 staged once into smem.
// persp = S3 / (sqrt(max(S1,eps))*sqrt(max(S2,eps)))
// ---------------------------------------------------------------------------
__global__ void __launch_bounds__(256) k_persp(const float* __restrict__ inp_a,
                                               float* __restrict__ out, int dup) {
    __shared__ __align__(16) float sW2[PP * DD];   // 40KB
    int tid = threadIdx.x;
#pragma unroll
    for (int i = 0; i < 10; i++)
        ((float4*)sW2)[tid + i * 256] = ((const float4*)g_W2)[tid + i * 256];
    __syncthreads();

    int lane = tid & 31;
    int w = tid >> 5;
    int row = blockIdx.x * 8 + w;

    const float4* a4p = (const float4*)(inp_a + (size_t)row * DD);
    const float4* h4p = (const float4*)(g_hmean + (size_t)row * DD);
    float4 a[4], h[4];
#pragma unroll
    for (int i = 0; i < 4; i++) { a[i] = a4p[lane + 32 * i]; h[i] = h4p[lane + 32 * i]; }

    for (int p = 0; p < PP; p++) {
        const float4* w4p = (const float4*)(sW2 + p * DD);
        float s1 = 0.f, s2 = 0.f, s3 = 0.f;
#pragma unroll
        for (int i = 0; i < 4; i++) {
            float4 wv = w4p[lane + 32 * i];   // already squared
            s1 += a[i].x * a[i].x * wv.x; s2 += h[i].x * h[i].x * wv.x; s3 += a[i].x * h[i].x * wv.x;
            s1 += a[i].y * a[i].y * wv.y; s2 += h[i].y * h[i].y * wv.y; s3 += a[i].y * h[i].y * wv.y;
            s1 += a[i].z * a[i].z * wv.z; s2 += h[i].z * h[i].z * wv.z; s3 += a[i].z * h[i].z * wv.z;
            s1 += a[i].w * a[i].w * wv.w; s2 += h[i].w * h[i].w * wv.w; s3 += a[i].w * h[i].w * wv.w;
        }
#pragma unroll
        for (int o = 16; o > 0; o >>= 1) {
            s1 += __shfl_xor_sync(0xffffffffu, s1, o);
            s2 += __shfl_xor_sync(0xffffffffu, s2, o);
            s3 += __shfl_xor_sync(0xffffffffu, s3, o);
        }
        if (lane == 0) {
            float v = s3 * rsqrtf(fmaxf(s1, EPSV)) * rsqrtf(fmaxf(s2, EPSV));
            out[(size_t)row * PP + p] = v;
            if (dup) out[(size_t)BB * TT * PP + (size_t)row * PP + p] = v;
        }
    }
}

// ---------------------------------------------------------------------------
extern "C" void kernel_launch(void* const* d_in, const int* in_sizes, int n_in,
                              void* d_out, int out_size) {
    const float* inp_a = (const float*)d_in[0];
    const float* inp_b = (const float*)d_in[1];
    const float* W     = (const float*)d_in[2];
    float* out = (float*)d_out;
    int dup = (out_size >= 2 * BB * TT * PP) ? 1 : 0;

    void *p_nbn_bf, *p_nbnT_bf, *p_nanT_bf, *p_alphaTb, *p_invcol, *p_hmean;
    cudaGetSymbolAddress(&p_nbn_bf, g_nbn_bf);
    cudaGetSymbolAddress(&p_nbnT_bf, g_nbnT_bf);
    cudaGetSymbolAddress(&p_nanT_bf, g_nanT_bf);
    cudaGetSymbolAddress(&p_alphaTb, g_alphaTb);
    cudaGetSymbolAddress(&p_invcol, g_invcol);
    cudaGetSymbolAddress(&p_hmean, g_hmean);

    // 1) normalize + transpose -> bf16  (+ W^2 precompute, independent)
    k_normT<<<dim3(TT / 16, BB, 2), 256>>>(inp_a, inp_b);
    k_w2<<<(PP * DD + 255) / 256, 256>>>(W);

    // 2) GEMM1: alphaTb[e][d] = bf16( sum_t nbnT[d,t]*nanT[e,t] )
    k_gemm_bf16<<<dim3(4, 4, BB), 256>>>(
        (const __nv_bfloat16*)p_nbnT_bf, TT, (size_t)DD * TT,
        (const __nv_bfloat16*)p_nanT_bf, TT, (size_t)DD * TT,
        p_alphaTb, (size_t)DD * DD, nullptr, TT, 1);

    // 3) inverse column norms from bf16 alphaT
    k_colnorm<<<(BB * DD) / 8, 256>>>();

    // 4) GEMM2: hmean[t][e] = (sum_d alphaTb[e,d]*nbn[t,d]) * invcol[e]
    k_gemm_bf16<<<dim3(4, 2, BB), 256>>>(
        (const __nv_bfloat16*)p_alphaTb, DD, (size_t)DD * DD,
        (const __nv_bfloat16*)p_nbn_bf, DD, (size_t)TT * DD,
        p_hmean, (size_t)TT * DD, (const float*)p_invcol, DD, 0);

    // 5) perspective scores (W^2 from smem)
    k_persp<<<BB * TT / 8, 256>>>(inp_a, out, dup);
}

// round 10
// speedup vs baseline: 1.5021x; 1.5021x over previous
#include <cuda_runtime.h>
#include <cuda_bf16.h>
#include <cstdint>

#define BB 32
#define TT 256
#define DD 512
#define PP 20
#define EPSV 1e-12f

// ---------------- scratch (__device__ globals; no cudaMalloc allowed) ------
__device__ __align__(16) __nv_bfloat16 g_nbn_bf [BB * TT * DD];   // [b][t][d]
__device__ __align__(16) __nv_bfloat16 g_nbnT_bf[BB * DD * TT];   // [b][d][t]
__device__ __align__(16) __nv_bfloat16 g_nanT_bf[BB * DD * TT];   // [b][d][t]
__device__ __align__(16) __nv_bfloat16 g_alphaTb[(size_t)BB * DD * DD]; // [b][e][d]
__device__ float g_invcol[BB * DD];                                // per (b,e)
__device__ __align__(16) float g_hmean[BB * TT * DD];              // [b][t][e]

__device__ __forceinline__ uint32_t smem_u32(const void* p) {
    return (uint32_t)__cvta_generic_to_shared(p);
}
// pack two fp32 -> bf16x2 (lo = x, hi = y), round-to-nearest-even
__device__ __forceinline__ uint32_t pack_bf2(float x, float y) {
    uint32_t r;
    asm("cvt.rn.bf16x2.f32 %0, %1, %2;" : "=r"(r) : "f"(y), "f"(x));
    return r;
}

// ---------------------------------------------------------------------------
// Kernel 1: row l2-normalize + transpose, bf16 outputs.
// ---------------------------------------------------------------------------
__global__ void __launch_bounds__(256) k_normT(const float* __restrict__ a,
                                               const float* __restrict__ b) {
    __shared__ float s[16 * 513];
    __shared__ float sinv[16];
    int which = blockIdx.z;
    int bb = blockIdx.y;
    int t0 = blockIdx.x * 16;
    const float* src = (which ? b : a) + ((size_t)bb * TT + t0) * DD;
    int tid = threadIdx.x;

#pragma unroll
    for (int i = 0; i < 8; i++) {
        int idx = tid + i * 256;
        int r = idx >> 7, c4 = idx & 127;
        float4 v = *(const float4*)(src + (size_t)r * DD + c4 * 4);
        float* sr = s + r * 513 + c4 * 4;
        sr[0] = v.x; sr[1] = v.y; sr[2] = v.z; sr[3] = v.w;
    }
    __syncthreads();

    int wid = tid >> 5, lid = tid & 31;
#pragma unroll
    for (int rr = 0; rr < 2; rr++) {
        int r = wid * 2 + rr;
        float ss = 0.f;
#pragma unroll
        for (int j = 0; j < 16; j++) { float v = s[r * 513 + lid + 32 * j]; ss += v * v; }
#pragma unroll
        for (int o = 16; o > 0; o >>= 1) ss += __shfl_xor_sync(0xffffffffu, ss, o);
        if (lid == 0) sinv[r] = rsqrtf(fmaxf(ss, EPSV));
    }
    __syncthreads();

    __nv_bfloat16* dstT = (which ? g_nbnT_bf : g_nanT_bf) + (size_t)bb * DD * TT;
#pragma unroll
    for (int i = 0; i < 8; i++) {
        int idx = tid + i * 256;
        int d = idx >> 2, jq = (idx & 3) * 4;
        float o0 = s[(jq + 0) * 513 + d] * sinv[jq + 0];
        float o1 = s[(jq + 1) * 513 + d] * sinv[jq + 1];
        float o2 = s[(jq + 2) * 513 + d] * sinv[jq + 2];
        float o3 = s[(jq + 3) * 513 + d] * sinv[jq + 3];
        uint2 u = make_uint2(pack_bf2(o0, o1), pack_bf2(o2, o3));
        *(uint2*)(dstT + (size_t)d * TT + t0 + jq) = u;
    }
    if (which) {
        __nv_bfloat16* dst = g_nbn_bf + ((size_t)bb * TT + t0) * DD;
#pragma unroll
        for (int i = 0; i < 8; i++) {
            int idx = tid + i * 256;
            int r = idx >> 7, c4 = idx & 127;
            float inv = sinv[r];
            float* sr = s + r * 513 + c4 * 4;
            uint2 u = make_uint2(pack_bf2(sr[0] * inv, sr[1] * inv),
                                 pack_bf2(sr[2] * inv, sr[3] * inv));
            *(uint2*)(dst + (size_t)r * DD + c4 * 4) = u;
        }
    }
}

// ---------------------------------------------------------------------------
// bf16 mma.sync GEMM, 3-stage cp.async pipeline, ldmatrix fragment loads.
// CTA tile 128x128, K-chunk 32. Store transposed: C[n*512 + m].
// out_bf16=1: bf16 store, no scale.  out_bf16=0: fp32 store * scale[m].
// ---------------------------------------------------------------------------
__global__ void __launch_bounds__(256, 2) k_gemm_bf16(
    const __nv_bfloat16* __restrict__ Ag, int lda, size_t strideA,
    const __nv_bfloat16* __restrict__ Bg, int ldb, size_t strideB,
    void* __restrict__ Cg, size_t strideC,
    const float* __restrict__ scale, int Ktot, int out_bf16) {
    __shared__ __align__(16) char sm[3 * 16384];  // 48KB

    int b = blockIdx.z;
    int m0 = blockIdx.x * 128, n0 = blockIdx.y * 128;
    const __nv_bfloat16* A  = Ag + (size_t)b * strideA + (size_t)m0 * lda;
    const __nv_bfloat16* Bp = Bg + (size_t)b * strideB + (size_t)n0 * ldb;

    int tid = threadIdx.x, lane = tid & 31, wid = tid >> 5;
    int wm = wid & 1, wn = wid >> 1;
    uint32_t smbase = smem_u32(sm);

    float acc[4][4][4];
#pragma unroll
    for (int i = 0; i < 4; i++)
#pragma unroll
        for (int j = 0; j < 4; j++)
#pragma unroll
            for (int k = 0; k < 4; k++) acc[i][j][k] = 0.f;

    int nkt = Ktot / 32;

    auto issue_chunk = [&](int kt) {
        uint32_t base = smbase + (uint32_t)(kt % 3) * 16384u;
        int k0 = kt * 32;
#pragma unroll
        for (int i = 0; i < 2; i++) {
            int idx = tid + i * 256;
            int r = idx >> 2, q = idx & 3;
            uint32_t off = (uint32_t)(r * 64 + ((q ^ ((r >> 1) & 3)) << 4));
            const __nv_bfloat16* srcA = A + (size_t)r * lda + k0 + q * 8;
            asm volatile("cp.async.cg.shared.global [%0], [%1], 16;"
                         :: "r"(base + off), "l"(srcA));
            const __nv_bfloat16* srcB = Bp + (size_t)r * ldb + k0 + q * 8;
            asm volatile("cp.async.cg.shared.global [%0], [%1], 16;"
                         :: "r"(base + 8192u + off), "l"(srcB));
        }
        asm volatile("cp.async.commit_group;");
    };

    issue_chunk(0);
    if (nkt > 1) issue_chunk(1);

    for (int kt = 0; kt < nkt; kt++) {
        asm volatile("cp.async.wait_group 1;" ::: "memory");
        __syncthreads();
        if (kt + 2 < nkt) issue_chunk(kt + 2);

        uint32_t baseA = smbase + (uint32_t)(kt % 3) * 16384u;
        uint32_t baseB = baseA + 8192u;

#pragma unroll
        for (int ks = 0; ks < 2; ks++) {
            uint32_t af[4][4], bf[4][2];
#pragma unroll
            for (int mt = 0; mt < 4; mt++) {
                int r = wm * 64 + mt * 16 + (lane & 15);
                int q = ks * 2 + (lane >> 4);
                uint32_t addr = baseA + (uint32_t)(r * 64 + ((q ^ ((r >> 1) & 3)) << 4));
                asm volatile("ldmatrix.sync.aligned.m8n8.x4.shared.b16 {%0,%1,%2,%3}, [%4];"
                             : "=r"(af[mt][0]), "=r"(af[mt][1]),
                               "=r"(af[mt][2]), "=r"(af[mt][3])
                             : "r"(addr));
            }
#pragma unroll
            for (int nt = 0; nt < 4; nt++) {
                int r = wn * 32 + nt * 8 + (lane & 7);
                int q = ks * 2 + ((lane >> 3) & 1);
                uint32_t addr = baseB + (uint32_t)(r * 64 + ((q ^ ((r >> 1) & 3)) << 4));
                asm volatile("ldmatrix.sync.aligned.m8n8.x2.shared.b16 {%0,%1}, [%2];"
                             : "=r"(bf[nt][0]), "=r"(bf[nt][1])
                             : "r"(addr));
            }
#pragma unroll
            for (int mt = 0; mt < 4; mt++)
#pragma unroll
                for (int nt = 0; nt < 4; nt++) {
                    asm volatile(
                        "mma.sync.aligned.m16n8k16.row.col.f32.bf16.bf16.f32 "
                        "{%0,%1,%2,%3}, {%4,%5,%6,%7}, {%8,%9}, {%0,%1,%2,%3};"
                        : "+f"(acc[mt][nt][0]), "+f"(acc[mt][nt][1]),
                          "+f"(acc[mt][nt][2]), "+f"(acc[mt][nt][3])
                        : "r"(af[mt][0]), "r"(af[mt][1]),
                          "r"(af[mt][2]), "r"(af[mt][3]),
                          "r"(bf[nt][0]), "r"(bf[nt][1]));
                }
        }
        __syncthreads();
    }

    // ---- epilogue ----
    if (out_bf16) {
        __nv_bfloat16* Cb = (__nv_bfloat16*)Cg + (size_t)b * strideC;
#pragma unroll
        for (int mt = 0; mt < 4; mt++) {
            int r0 = m0 + wm * 64 + mt * 16 + (lane >> 2);
#pragma unroll
            for (int nt = 0; nt < 4; nt++) {
                int c0 = n0 + wn * 32 + nt * 8 + (lane & 3) * 2;
                Cb[(size_t)c0 * 512 + r0]           = __float2bfloat16(acc[mt][nt][0]);
                Cb[(size_t)(c0 + 1) * 512 + r0]     = __float2bfloat16(acc[mt][nt][1]);
                Cb[(size_t)c0 * 512 + r0 + 8]       = __float2bfloat16(acc[mt][nt][2]);
                Cb[(size_t)(c0 + 1) * 512 + r0 + 8] = __float2bfloat16(acc[mt][nt][3]);
            }
        }
    } else {
        float* Cb = (float*)Cg + (size_t)b * strideC;
        const float* scb = scale + (size_t)b * DD;
#pragma unroll
        for (int mt = 0; mt < 4; mt++) {
            int r0 = m0 + wm * 64 + mt * 16 + (lane >> 2);
            float sc0 = scb[r0];
            float sc1 = scb[r0 + 8];
#pragma unroll
            for (int nt = 0; nt < 4; nt++) {
                int c0 = n0 + wn * 32 + nt * 8 + (lane & 3) * 2;
                Cb[(size_t)c0 * 512 + r0]           = acc[mt][nt][0] * sc0;
                Cb[(size_t)(c0 + 1) * 512 + r0]     = acc[mt][nt][1] * sc0;
                Cb[(size_t)c0 * 512 + r0 + 8]       = acc[mt][nt][2] * sc1;
                Cb[(size_t)(c0 + 1) * 512 + r0 + 8] = acc[mt][nt][3] * sc1;
            }
        }
    }
}

// ---------------------------------------------------------------------------
// Row norms of bf16 alphaT -> invcol. One warp per (b,e) row (512 bf16 = 1KB).
// ---------------------------------------------------------------------------
__global__ void __launch_bounds__(256) k_colnorm() {
    int gw = (blockIdx.x * blockDim.x + threadIdx.x) >> 5;
    int lane = threadIdx.x & 31;
    if (gw >= BB * DD) return;
    const uint4* r4 = (const uint4*)(g_alphaTb + (size_t)gw * DD);
    float ss = 0.f;
#pragma unroll
    for (int i = 0; i < 2; i++) {
        uint4 v = r4[lane + 32 * i];
        uint32_t ws[4] = {v.x, v.y, v.z, v.w};
#pragma unroll
        for (int j = 0; j < 4; j++) {
            float2 f = __bfloat1622float2(*(__nv_bfloat162*)&ws[j]);
            ss += f.x * f.x + f.y * f.y;
        }
    }
#pragma unroll
    for (int o = 16; o > 0; o >>= 1) ss += __shfl_xor_sync(0xffffffffu, ss, o);
    if (lane == 0) g_invcol[gw] = rsqrtf(fmaxf(ss, EPSV));
}

// ---------------------------------------------------------------------------
// Perspective scores (R7 shape: 128 thr, 1 row/block, warp w -> persps 5w..5w+4).
// persp = S3 / (sqrt(max(S1,eps))*sqrt(max(S2,eps)))
// ---------------------------------------------------------------------------
__global__ void __launch_bounds__(128) k_persp(const float* __restrict__ inp_a,
                                               const float* __restrict__ W,
                                               float* __restrict__ out, int dup) {
    int row = blockIdx.x;
    int lane = threadIdx.x & 31;
    int w = threadIdx.x >> 5;

    const float4* a4p = (const float4*)(inp_a + (size_t)row * DD);
    const float4* h4p = (const float4*)(g_hmean + (size_t)row * DD);
    float4 a[4], h[4];
#pragma unroll
    for (int i = 0; i < 4; i++) { a[i] = a4p[lane + 32 * i]; h[i] = h4p[lane + 32 * i]; }

#pragma unroll
    for (int pp = 0; pp < 5; pp++) {
        int p = w * 5 + pp;
        const float4* w4p = (const float4*)(W + (size_t)p * DD);
        float s1 = 0.f, s2 = 0.f, s3 = 0.f;
#pragma unroll
        for (int i = 0; i < 4; i++) {
            float4 wv = w4p[lane + 32 * i];
            float w2;
            w2 = wv.x * wv.x; s1 += a[i].x * a[i].x * w2; s2 += h[i].x * h[i].x * w2; s3 += a[i].x * h[i].x * w2;
            w2 = wv.y * wv.y; s1 += a[i].y * a[i].y * w2; s2 += h[i].y * h[i].y * w2; s3 += a[i].y * h[i].y * w2;
            w2 = wv.z * wv.z; s1 += a[i].z * a[i].z * w2; s2 += h[i].z * h[i].z * w2; s3 += a[i].z * h[i].z * w2;
            w2 = wv.w * wv.w; s1 += a[i].w * a[i].w * w2; s2 += h[i].w * h[i].w * w2; s3 += a[i].w * h[i].w * w2;
        }
#pragma unroll
        for (int o = 16; o > 0; o >>= 1) {
            s1 += __shfl_xor_sync(0xffffffffu, s1, o);
            s2 += __shfl_xor_sync(0xffffffffu, s2, o);
            s3 += __shfl_xor_sync(0xffffffffu, s3, o);
        }
        if (lane == 0) {
            float v = s3 * rsqrtf(fmaxf(s1, EPSV)) * rsqrtf(fmaxf(s2, EPSV));
            out[(size_t)row * PP + p] = v;
            if (dup) out[(size_t)BB * TT * PP + (size_t)row * PP + p] = v;
        }
    }
}

// ---------------------------------------------------------------------------
extern "C" void kernel_launch(void* const* d_in, const int* in_sizes, int n_in,
                              void* d_out, int out_size) {
    const float* inp_a = (const float*)d_in[0];
    const float* inp_b = (const float*)d_in[1];
    const float* W     = (const float*)d_in[2];
    float* out = (float*)d_out;
    int dup = (out_size >= 2 * BB * TT * PP) ? 1 : 0;

    void *p_nbn_bf, *p_nbnT_bf, *p_nanT_bf, *p_alphaTb, *p_invcol, *p_hmean;
    cudaGetSymbolAddress(&p_nbn_bf, g_nbn_bf);
    cudaGetSymbolAddress(&p_nbnT_bf, g_nbnT_bf);
    cudaGetSymbolAddress(&p_nanT_bf, g_nanT_bf);
    cudaGetSymbolAddress(&p_alphaTb, g_alphaTb);
    cudaGetSymbolAddress(&p_invcol, g_invcol);
    cudaGetSymbolAddress(&p_hmean, g_hmean);

    // 1) normalize + transpose -> bf16
    k_normT<<<dim3(TT / 16, BB, 2), 256>>>(inp_a, inp_b);

    // 2) GEMM1: alphaTb[e][d] = bf16( sum_t nbnT[d,t]*nanT[e,t] )
    k_gemm_bf16<<<dim3(4, 4, BB), 256>>>(
        (const __nv_bfloat16*)p_nbnT_bf, TT, (size_t)DD * TT,
        (const __nv_bfloat16*)p_nanT_bf, TT, (size_t)DD * TT,
        p_alphaTb, (size_t)DD * DD, nullptr, TT, 1);

    // 3) inverse column norms from bf16 alphaT
    k_colnorm<<<(BB * DD) / 8, 256>>>();

    // 4) GEMM2: hmean[t][e] = (sum_d alphaTb[e,d]*nbn[t,d]) * invcol[e]
    k_gemm_bf16<<<dim3(4, 2, BB), 256>>>(
        (const __nv_bfloat16*)p_alphaTb, DD, (size_t)DD * DD,
        (const __nv_bfloat16*)p_nbn_bf, DD, (size_t)TT * DD,
        p_hmean, (size_t)TT * DD, (const float*)p_invcol, DD, 0);

    // 5) perspective scores (R7 shape)
    k_persp<<<BB * TT, 128>>>(inp_a, W, out, dup);
}

// round 11
// speedup vs baseline: 1.5727x; 1.0470x over previous
#include <cuda_runtime.h>
#include <cuda_bf16.h>
#include <cstdint>

#define BB 32
#define TT 256
#define DD 512
#define PP 20
#define EPSV 1e-12f

// ---------------- scratch (__device__ globals; no cudaMalloc allowed) ------
__device__ __align__(16) __nv_bfloat16 g_nbn_bf [BB * TT * DD];   // [b][t][d]
__device__ __align__(16) __nv_bfloat16 g_nbnT_bf[BB * DD * TT];   // [b][d][t]
__device__ __align__(16) __nv_bfloat16 g_nanT_bf[BB * DD * TT];   // [b][d][t]
__device__ __align__(16) __nv_bfloat16 g_alphaTb[(size_t)BB * DD * DD]; // [b][e][d]
__device__ __align__(16) float g_colpart[BB * 4 * DD];            // per (b, mtile, e)
__device__ __align__(16) __nv_bfloat16 g_hmean_bf[BB * TT * DD];  // [b][t][e]

__device__ __forceinline__ uint32_t smem_u32(const void* p) {
    return (uint32_t)__cvta_generic_to_shared(p);
}
// pack two fp32 -> bf16x2 (lo = x, hi = y), round-to-nearest-even
__device__ __forceinline__ uint32_t pack_bf2(float x, float y) {
    uint32_t r;
    asm("cvt.rn.bf16x2.f32 %0, %1, %2;" : "=r"(r) : "f"(y), "f"(x));
    return r;
}

// ---------------------------------------------------------------------------
// Kernel 1: row l2-normalize + transpose, bf16 outputs.
// ---------------------------------------------------------------------------
__global__ void __launch_bounds__(256) k_normT(const float* __restrict__ a,
                                               const float* __restrict__ b) {
    __shared__ float s[16 * 513];
    __shared__ float sinv[16];
    int which = blockIdx.z;
    int bb = blockIdx.y;
    int t0 = blockIdx.x * 16;
    const float* src = (which ? b : a) + ((size_t)bb * TT + t0) * DD;
    int tid = threadIdx.x;

#pragma unroll
    for (int i = 0; i < 8; i++) {
        int idx = tid + i * 256;
        int r = idx >> 7, c4 = idx & 127;
        float4 v = *(const float4*)(src + (size_t)r * DD + c4 * 4);
        float* sr = s + r * 513 + c4 * 4;
        sr[0] = v.x; sr[1] = v.y; sr[2] = v.z; sr[3] = v.w;
    }
    __syncthreads();

    int wid = tid >> 5, lid = tid & 31;
#pragma unroll
    for (int rr = 0; rr < 2; rr++) {
        int r = wid * 2 + rr;
        float ss = 0.f;
#pragma unroll
        for (int j = 0; j < 16; j++) { float v = s[r * 513 + lid + 32 * j]; ss += v * v; }
#pragma unroll
        for (int o = 16; o > 0; o >>= 1) ss += __shfl_xor_sync(0xffffffffu, ss, o);
        if (lid == 0) sinv[r] = rsqrtf(fmaxf(ss, EPSV));
    }
    __syncthreads();

    __nv_bfloat16* dstT = (which ? g_nbnT_bf : g_nanT_bf) + (size_t)bb * DD * TT;
#pragma unroll
    for (int i = 0; i < 8; i++) {
        int idx = tid + i * 256;
        int d = idx >> 2, jq = (idx & 3) * 4;
        float o0 = s[(jq + 0) * 513 + d] * sinv[jq + 0];
        float o1 = s[(jq + 1) * 513 + d] * sinv[jq + 1];
        float o2 = s[(jq + 2) * 513 + d] * sinv[jq + 2];
        float o3 = s[(jq + 3) * 513 + d] * sinv[jq + 3];
        uint2 u = make_uint2(pack_bf2(o0, o1), pack_bf2(o2, o3));
        *(uint2*)(dstT + (size_t)d * TT + t0 + jq) = u;
    }
    if (which) {
        __nv_bfloat16* dst = g_nbn_bf + ((size_t)bb * TT + t0) * DD;
#pragma unroll
        for (int i = 0; i < 8; i++) {
            int idx = tid + i * 256;
            int r = idx >> 7, c4 = idx & 127;
            float inv = sinv[r];
            float* sr = s + r * 513 + c4 * 4;
            uint2 u = make_uint2(pack_bf2(sr[0] * inv, sr[1] * inv),
                                 pack_bf2(sr[2] * inv, sr[3] * inv));
            *(uint2*)(dst + (size_t)r * DD + c4 * 4) = u;
        }
    }
}

// ---------------------------------------------------------------------------
// bf16 mma.sync GEMM, 3-stage cp.async pipeline, ldmatrix fragment loads.
// CTA tile 128x128, K-chunk 32. Store transposed: C[n*512 + m], bf16.
// mode 1 (GEMM1): also emit per-CTA column sum-of-squares partials
//                 colpart[(b*4 + blockIdx.x)*DD + n]  (n = e, sum over m-tile d's)
// mode 2 (GEMM2): scale output by rsqrt(max(sum_j colpart[j][m], eps))
// ---------------------------------------------------------------------------
__global__ void __launch_bounds__(256, 2) k_gemm_bf16(
    const __nv_bfloat16* __restrict__ Ag, int lda, size_t strideA,
    const __nv_bfloat16* __restrict__ Bg, int ldb, size_t strideB,
    __nv_bfloat16* __restrict__ Cg, size_t strideC,
    float* __restrict__ colpart, int Ktot, int mode) {
    __shared__ __align__(16) char sm[3 * 16384];  // 48KB

    int b = blockIdx.z;
    int m0 = blockIdx.x * 128, n0 = blockIdx.y * 128;
    const __nv_bfloat16* A  = Ag + (size_t)b * strideA + (size_t)m0 * lda;
    const __nv_bfloat16* Bp = Bg + (size_t)b * strideB + (size_t)n0 * ldb;

    int tid = threadIdx.x, lane = tid & 31, wid = tid >> 5;
    int wm = wid & 1, wn = wid >> 1;
    uint32_t smbase = smem_u32(sm);

    float acc[4][4][4];
#pragma unroll
    for (int i = 0; i < 4; i++)
#pragma unroll
        for (int j = 0; j < 4; j++)
#pragma unroll
            for (int k = 0; k < 4; k++) acc[i][j][k] = 0.f;

    int nkt = Ktot / 32;

    auto issue_chunk = [&](int kt) {
        uint32_t base = smbase + (uint32_t)(kt % 3) * 16384u;
        int k0 = kt * 32;
#pragma unroll
        for (int i = 0; i < 2; i++) {
            int idx = tid + i * 256;
            int r = idx >> 2, q = idx & 3;
            uint32_t off = (uint32_t)(r * 64 + ((q ^ ((r >> 1) & 3)) << 4));
            const __nv_bfloat16* srcA = A + (size_t)r * lda + k0 + q * 8;
            asm volatile("cp.async.cg.shared.global [%0], [%1], 16;"
                         :: "r"(base + off), "l"(srcA));
            const __nv_bfloat16* srcB = Bp + (size_t)r * ldb + k0 + q * 8;
            asm volatile("cp.async.cg.shared.global [%0], [%1], 16;"
                         :: "r"(base + 8192u + off), "l"(srcB));
        }
        asm volatile("cp.async.commit_group;");
    };

    issue_chunk(0);
    if (nkt > 1) issue_chunk(1);

    for (int kt = 0; kt < nkt; kt++) {
        asm volatile("cp.async.wait_group 1;" ::: "memory");
        __syncthreads();
        if (kt + 2 < nkt) issue_chunk(kt + 2);

        uint32_t baseA = smbase + (uint32_t)(kt % 3) * 16384u;
        uint32_t baseB = baseA + 8192u;

#pragma unroll
        for (int ks = 0; ks < 2; ks++) {
            uint32_t af[4][4], bf[4][2];
#pragma unroll
            for (int mt = 0; mt < 4; mt++) {
                int r = wm * 64 + mt * 16 + (lane & 15);
                int q = ks * 2 + (lane >> 4);
                uint32_t addr = baseA + (uint32_t)(r * 64 + ((q ^ ((r >> 1) & 3)) << 4));
                asm volatile("ldmatrix.sync.aligned.m8n8.x4.shared.b16 {%0,%1,%2,%3}, [%4];"
                             : "=r"(af[mt][0]), "=r"(af[mt][1]),
                               "=r"(af[mt][2]), "=r"(af[mt][3])
                             : "r"(addr));
            }
#pragma unroll
            for (int nt = 0; nt < 4; nt++) {
                int r = wn * 32 + nt * 8 + (lane & 7);
                int q = ks * 2 + ((lane >> 3) & 1);
                uint32_t addr = baseB + (uint32_t)(r * 64 + ((q ^ ((r >> 1) & 3)) << 4));
                asm volatile("ldmatrix.sync.aligned.m8n8.x2.shared.b16 {%0,%1}, [%2];"
                             : "=r"(bf[nt][0]), "=r"(bf[nt][1])
                             : "r"(addr));
            }
#pragma unroll
            for (int mt = 0; mt < 4; mt++)
#pragma unroll
                for (int nt = 0; nt < 4; nt++) {
                    asm volatile(
                        "mma.sync.aligned.m16n8k16.row.col.f32.bf16.bf16.f32 "
                        "{%0,%1,%2,%3}, {%4,%5,%6,%7}, {%8,%9}, {%0,%1,%2,%3};"
                        : "+f"(acc[mt][nt][0]), "+f"(acc[mt][nt][1]),
                          "+f"(acc[mt][nt][2]), "+f"(acc[mt][nt][3])
                        : "r"(af[mt][0]), "r"(af[mt][1]),
                          "r"(af[mt][2]), "r"(af[mt][3]),
                          "r"(bf[nt][0]), "r"(bf[nt][1]));
                }
        }
        __syncthreads();
    }

    // ---- epilogue ----
    __nv_bfloat16* Cb = Cg + (size_t)b * strideC;

    if (mode == 1) {
        // bf16 store + column sumsq partials
#pragma unroll
        for (int mt = 0; mt < 4; mt++) {
            int r0 = m0 + wm * 64 + mt * 16 + (lane >> 2);
#pragma unroll
            for (int nt = 0; nt < 4; nt++) {
                int c0 = n0 + wn * 32 + nt * 8 + (lane & 3) * 2;
                Cb[(size_t)c0 * 512 + r0]           = __float2bfloat16(acc[mt][nt][0]);
                Cb[(size_t)(c0 + 1) * 512 + r0]     = __float2bfloat16(acc[mt][nt][1]);
                Cb[(size_t)c0 * 512 + r0 + 8]       = __float2bfloat16(acc[mt][nt][2]);
                Cb[(size_t)(c0 + 1) * 512 + r0 + 8] = __float2bfloat16(acc[mt][nt][3]);
            }
        }
        // per-(nt, col-pair) sumsq over this warp's 8 m values, then over lanes
        float p0[4], p1[4];
#pragma unroll
        for (int nt = 0; nt < 4; nt++) {
            float s0 = 0.f, s1 = 0.f;
#pragma unroll
            for (int mt = 0; mt < 4; mt++) {
                s0 += acc[mt][nt][0] * acc[mt][nt][0] + acc[mt][nt][2] * acc[mt][nt][2];
                s1 += acc[mt][nt][1] * acc[mt][nt][1] + acc[mt][nt][3] * acc[mt][nt][3];
            }
#pragma unroll
            for (int o = 4; o < 32; o <<= 1) {
                s0 += __shfl_xor_sync(0xffffffffu, s0, o);
                s1 += __shfl_xor_sync(0xffffffffu, s1, o);
            }
            p0[nt] = s0; p1[nt] = s1;
        }
        float* psum = (float*)sm;   // 128 floats, reuse staging smem
        if (wm == 0 && lane < 4) {
#pragma unroll
            for (int nt = 0; nt < 4; nt++) {
                int idx = wn * 32 + nt * 8 + lane * 2;
                psum[idx] = p0[nt]; psum[idx + 1] = p1[nt];
            }
        }
        __syncthreads();
        if (wm == 1 && lane < 4) {
#pragma unroll
            for (int nt = 0; nt < 4; nt++) {
                int idx = wn * 32 + nt * 8 + lane * 2;
                psum[idx] += p0[nt]; psum[idx + 1] += p1[nt];
            }
        }
        __syncthreads();
        if (tid < 128)
            colpart[((size_t)b * 4 + blockIdx.x) * DD + n0 + tid] = psum[tid];
    } else {
        // mode 2: scale by rsqrt of summed column partials, bf16 store
        const float* cp = colpart + (size_t)b * 4 * DD;
#pragma unroll
        for (int mt = 0; mt < 4; mt++) {
            int r0 = m0 + wm * 64 + mt * 16 + (lane >> 2);
            float cs0 = cp[r0] + cp[DD + r0] + cp[2 * DD + r0] + cp[3 * DD + r0];
            float cs1 = cp[r0 + 8] + cp[DD + r0 + 8] + cp[2 * DD + r0 + 8] + cp[3 * DD + r0 + 8];
            float sc0 = rsqrtf(fmaxf(cs0, EPSV));
            float sc1 = rsqrtf(fmaxf(cs1, EPSV));
#pragma unroll
            for (int nt = 0; nt < 4; nt++) {
                int c0 = n0 + wn * 32 + nt * 8 + (lane & 3) * 2;
                Cb[(size_t)c0 * 512 + r0]           = __float2bfloat16(acc[mt][nt][0] * sc0);
                Cb[(size_t)(c0 + 1) * 512 + r0]     = __float2bfloat16(acc[mt][nt][1] * sc0);
                Cb[(size_t)c0 * 512 + r0 + 8]       = __float2bfloat16(acc[mt][nt][2] * sc1);
                Cb[(size_t)(c0 + 1) * 512 + r0 + 8] = __float2bfloat16(acc[mt][nt][3] * sc1);
            }
        }
    }
}

// ---------------------------------------------------------------------------
// Perspective scores (128 thr, 1 row/block, warp w -> persps 5w..5w+4).
// h (= hmean) read as bf16. persp = S3 / (sqrt(max(S1,eps))*sqrt(max(S2,eps)))
// ---------------------------------------------------------------------------
__global__ void __launch_bounds__(128) k_persp(const float* __restrict__ inp_a,
                                               const float* __restrict__ W,
                                               float* __restrict__ out, int dup) {
    int row = blockIdx.x;
    int lane = threadIdx.x & 31;
    int w = threadIdx.x >> 5;

    const float4* a4p = (const float4*)(inp_a + (size_t)row * DD);
    const uint2* h2p = (const uint2*)(g_hmean_bf + (size_t)row * DD);
    float4 a[4], h[4];
#pragma unroll
    for (int i = 0; i < 4; i++) {
        a[i] = a4p[lane + 32 * i];
        uint2 hu = h2p[lane + 32 * i];   // 4 bf16, dims match a[i]
        float2 f0 = __bfloat1622float2(*(__nv_bfloat162*)&hu.x);
        float2 f1 = __bfloat1622float2(*(__nv_bfloat162*)&hu.y);
        h[i] = make_float4(f0.x, f0.y, f1.x, f1.y);
    }

#pragma unroll
    for (int pp = 0; pp < 5; pp++) {
        int p = w * 5 + pp;
        const float4* w4p = (const float4*)(W + (size_t)p * DD);
        float s1 = 0.f, s2 = 0.f, s3 = 0.f;
#pragma unroll
        for (int i = 0; i < 4; i++) {
            float4 wv = w4p[lane + 32 * i];
            float w2;
            w2 = wv.x * wv.x; s1 += a[i].x * a[i].x * w2; s2 += h[i].x * h[i].x * w2; s3 += a[i].x * h[i].x * w2;
            w2 = wv.y * wv.y; s1 += a[i].y * a[i].y * w2; s2 += h[i].y * h[i].y * w2; s3 += a[i].y * h[i].y * w2;
            w2 = wv.z * wv.z; s1 += a[i].z * a[i].z * w2; s2 += h[i].z * h[i].z * w2; s3 += a[i].z * h[i].z * w2;
            w2 = wv.w * wv.w; s1 += a[i].w * a[i].w * w2; s2 += h[i].w * h[i].w * w2; s3 += a[i].w * h[i].w * w2;
        }
#pragma unroll
        for (int o = 16; o > 0; o >>= 1) {
            s1 += __shfl_xor_sync(0xffffffffu, s1, o);
            s2 += __shfl_xor_sync(0xffffffffu, s2, o);
            s3 += __shfl_xor_sync(0xffffffffu, s3, o);
        }
        if (lane == 0) {
            float v = s3 * rsqrtf(fmaxf(s1, EPSV)) * rsqrtf(fmaxf(s2, EPSV));
            out[(size_t)row * PP + p] = v;
            if (dup) out[(size_t)BB * TT * PP + (size_t)row * PP + p] = v;
        }
    }
}

// ---------------------------------------------------------------------------
extern "C" void kernel_launch(void* const* d_in, const int* in_sizes, int n_in,
                              void* d_out, int out_size) {
    const float* inp_a = (const float*)d_in[0];
    const float* inp_b = (const float*)d_in[1];
    const float* W     = (const float*)d_in[2];
    float* out = (float*)d_out;
    int dup = (out_size >= 2 * BB * TT * PP) ? 1 : 0;

    void *p_nbn_bf, *p_nbnT_bf, *p_nanT_bf, *p_alphaTb, *p_colpart, *p_hmean_bf;
    cudaGetSymbolAddress(&p_nbn_bf, g_nbn_bf);
    cudaGetSymbolAddress(&p_nbnT_bf, g_nbnT_bf);
    cudaGetSymbolAddress(&p_nanT_bf, g_nanT_bf);
    cudaGetSymbolAddress(&p_alphaTb, g_alphaTb);
    cudaGetSymbolAddress(&p_colpart, g_colpart);
    cudaGetSymbolAddress(&p_hmean_bf, g_hmean_bf);

    // 1) normalize + transpose -> bf16
    k_normT<<<dim3(TT / 16, BB, 2), 256>>>(inp_a, inp_b);

    // 2) GEMM1: alphaTb[e][d] = bf16( sum_t nbnT[d,t]*nanT[e,t] ) + colpart sumsq
    k_gemm_bf16<<<dim3(4, 4, BB), 256>>>(
        (const __nv_bfloat16*)p_nbnT_bf, TT, (size_t)DD * TT,
        (const __nv_bfloat16*)p_nanT_bf, TT, (size_t)DD * TT,
        (__nv_bfloat16*)p_alphaTb, (size_t)DD * DD,
        (float*)p_colpart, TT, 1);

    // 3) GEMM2: hmean_bf[t][e] = bf16( (sum_d alphaTb[e,d]*nbn[t,d]) * invcol[e] )
    k_gemm_bf16<<<dim3(4, 2, BB), 256>>>(
        (const __nv_bfloat16*)p_alphaTb, DD, (size_t)DD * DD,
        (const __nv_bfloat16*)p_nbn_bf, DD, (size_t)TT * DD,
        (__nv_bfloat16*)p_hmean_bf, (size_t)TT * DD,
        (float*)p_colpart, DD, 2);

    // 4) perspective scores
    k_persp<<<BB * TT, 128>>>(inp_a, W, out, dup);
}

// round 12
// speedup vs baseline: 1.6400x; 1.0428x over previous
#include <cuda_runtime.h>
#include <cuda_bf16.h>
#include <cstdint>

#define BB 32
#define TT 256
#define DD 512
#define PP 20
#define EPSV 1e-12f

// ---------------- scratch (__device__ globals; no cudaMalloc allowed) ------
__device__ __align__(16) __nv_bfloat16 g_nbn_bf [BB * TT * DD];   // [b][t][d]
__device__ __align__(16) __nv_bfloat16 g_nbnT_bf[BB * DD * TT];   // [b][d][t]
__device__ __align__(16) __nv_bfloat16 g_nanT_bf[BB * DD * TT];   // [b][d][t]
__device__ __align__(16) __nv_bfloat16 g_alphaTb[(size_t)BB * DD * DD]; // [b][e][d]
__device__ __align__(16) float g_colpart[BB * 4 * DD];            // per (b, mtile, e)
__device__ __align__(16) __nv_bfloat16 g_hmean_bf[BB * TT * DD];  // [b][t][e]

__device__ __forceinline__ uint32_t smem_u32(const void* p) {
    return (uint32_t)__cvta_generic_to_shared(p);
}
// pack two fp32 -> bf16x2 (lo = x, hi = y), round-to-nearest-even
__device__ __forceinline__ uint32_t pack_bf2(float x, float y) {
    uint32_t r;
    asm("cvt.rn.bf16x2.f32 %0, %1, %2;" : "=r"(r) : "f"(y), "f"(x));
    return r;
}

// ---------------------------------------------------------------------------
// Kernel 1: row l2-normalize + transpose, bf16 outputs.
// ---------------------------------------------------------------------------
__global__ void __launch_bounds__(256) k_normT(const float* __restrict__ a,
                                               const float* __restrict__ b) {
    __shared__ float s[16 * 513];
    __shared__ float sinv[16];
    int which = blockIdx.z;
    int bb = blockIdx.y;
    int t0 = blockIdx.x * 16;
    const float* src = (which ? b : a) + ((size_t)bb * TT + t0) * DD;
    int tid = threadIdx.x;

#pragma unroll
    for (int i = 0; i < 8; i++) {
        int idx = tid + i * 256;
        int r = idx >> 7, c4 = idx & 127;
        float4 v = *(const float4*)(src + (size_t)r * DD + c4 * 4);
        float* sr = s + r * 513 + c4 * 4;
        sr[0] = v.x; sr[1] = v.y; sr[2] = v.z; sr[3] = v.w;
    }
    __syncthreads();

    int wid = tid >> 5, lid = tid & 31;
#pragma unroll
    for (int rr = 0; rr < 2; rr++) {
        int r = wid * 2 + rr;
        float ss = 0.f;
#pragma unroll
        for (int j = 0; j < 16; j++) { float v = s[r * 513 + lid + 32 * j]; ss += v * v; }
#pragma unroll
        for (int o = 16; o > 0; o >>= 1) ss += __shfl_xor_sync(0xffffffffu, ss, o);
        if (lid == 0) sinv[r] = rsqrtf(fmaxf(ss, EPSV));
    }
    __syncthreads();

    __nv_bfloat16* dstT = (which ? g_nbnT_bf : g_nanT_bf) + (size_t)bb * DD * TT;
#pragma unroll
    for (int i = 0; i < 8; i++) {
        int idx = tid + i * 256;
        int d = idx >> 2, jq = (idx & 3) * 4;
        float o0 = s[(jq + 0) * 513 + d] * sinv[jq + 0];
        float o1 = s[(jq + 1) * 513 + d] * sinv[jq + 1];
        float o2 = s[(jq + 2) * 513 + d] * sinv[jq + 2];
        float o3 = s[(jq + 3) * 513 + d] * sinv[jq + 3];
        uint2 u = make_uint2(pack_bf2(o0, o1), pack_bf2(o2, o3));
        *(uint2*)(dstT + (size_t)d * TT + t0 + jq) = u;
    }
    if (which) {
        __nv_bfloat16* dst = g_nbn_bf + ((size_t)bb * TT + t0) * DD;
#pragma unroll
        for (int i = 0; i < 8; i++) {
            int idx = tid + i * 256;
            int r = idx >> 7, c4 = idx & 127;
            float inv = sinv[r];
            float* sr = s + r * 513 + c4 * 4;
            uint2 u = make_uint2(pack_bf2(sr[0] * inv, sr[1] * inv),
                                 pack_bf2(sr[2] * inv, sr[3] * inv));
            *(uint2*)(dst + (size_t)r * DD + c4 * 4) = u;
        }
    }
}

// ---------------------------------------------------------------------------
// bf16 mma.sync GEMM, 4-stage cp.async pipeline, one barrier per K-chunk.
// CTA tile 128x128, K-chunk 32. Store transposed: C[n*512 + m], bf16.
// mode 1 (GEMM1): also emit per-CTA column sum-of-squares partials
// mode 2 (GEMM2): scale output by rsqrt(max(sum_j colpart[j][m], eps))
// ---------------------------------------------------------------------------
__global__ void __launch_bounds__(256, 2) k_gemm_bf16(
    const __nv_bfloat16* __restrict__ Ag, int lda, size_t strideA,
    const __nv_bfloat16* __restrict__ Bg, int ldb, size_t strideB,
    __nv_bfloat16* __restrict__ Cg, size_t strideC,
    float* __restrict__ colpart, int Ktot, int mode) {
    __shared__ __align__(16) char sm[4 * 16384];  // 64KB: 4 x (A 8KB + B 8KB)

    int b = blockIdx.z;
    int m0 = blockIdx.x * 128, n0 = blockIdx.y * 128;
    const __nv_bfloat16* A  = Ag + (size_t)b * strideA + (size_t)m0 * lda;
    const __nv_bfloat16* Bp = Bg + (size_t)b * strideB + (size_t)n0 * ldb;

    int tid = threadIdx.x, lane = tid & 31, wid = tid >> 5;
    int wm = wid & 1, wn = wid >> 1;
    uint32_t smbase = smem_u32(sm);

    float acc[4][4][4];
#pragma unroll
    for (int i = 0; i < 4; i++)
#pragma unroll
        for (int j = 0; j < 4; j++)
#pragma unroll
            for (int k = 0; k < 4; k++) acc[i][j][k] = 0.f;

    int nkt = Ktot / 32;

    auto issue_chunk = [&](int kt) {
        uint32_t base = smbase + (uint32_t)(kt & 3) * 16384u;
        int k0 = kt * 32;
#pragma unroll
        for (int i = 0; i < 2; i++) {
            int idx = tid + i * 256;
            int r = idx >> 2, q = idx & 3;
            uint32_t off = (uint32_t)(r * 64 + ((q ^ ((r >> 1) & 3)) << 4));
            const __nv_bfloat16* srcA = A + (size_t)r * lda + k0 + q * 8;
            asm volatile("cp.async.cg.shared.global [%0], [%1], 16;"
                         :: "r"(base + off), "l"(srcA));
            const __nv_bfloat16* srcB = Bp + (size_t)r * ldb + k0 + q * 8;
            asm volatile("cp.async.cg.shared.global [%0], [%1], 16;"
                         :: "r"(base + 8192u + off), "l"(srcB));
        }
        asm volatile("cp.async.commit_group;");
    };

    issue_chunk(0);
    issue_chunk(1);
    issue_chunk(2);

    for (int kt = 0; kt < nkt; kt++) {
        asm volatile("cp.async.wait_group 2;" ::: "memory");
        __syncthreads();   // orders: chunk kt visible AND all warps done computing kt-1
        if (kt + 3 < nkt) issue_chunk(kt + 3);

        uint32_t baseA = smbase + (uint32_t)(kt & 3) * 16384u;
        uint32_t baseB = baseA + 8192u;

#pragma unroll
        for (int ks = 0; ks < 2; ks++) {
            uint32_t af[4][4], bf[4][2];
#pragma unroll
            for (int mt = 0; mt < 4; mt++) {
                int r = wm * 64 + mt * 16 + (lane & 15);
                int q = ks * 2 + (lane >> 4);
                uint32_t addr = baseA + (uint32_t)(r * 64 + ((q ^ ((r >> 1) & 3)) << 4));
                asm volatile("ldmatrix.sync.aligned.m8n8.x4.shared.b16 {%0,%1,%2,%3}, [%4];"
                             : "=r"(af[mt][0]), "=r"(af[mt][1]),
                               "=r"(af[mt][2]), "=r"(af[mt][3])
                             : "r"(addr));
            }
#pragma unroll
            for (int nt = 0; nt < 4; nt++) {
                int r = wn * 32 + nt * 8 + (lane & 7);
                int q = ks * 2 + ((lane >> 3) & 1);
                uint32_t addr = baseB + (uint32_t)(r * 64 + ((q ^ ((r >> 1) & 3)) << 4));
                asm volatile("ldmatrix.sync.aligned.m8n8.x2.shared.b16 {%0,%1}, [%2];"
                             : "=r"(bf[nt][0]), "=r"(bf[nt][1])
                             : "r"(addr));
            }
#pragma unroll
            for (int mt = 0; mt < 4; mt++)
#pragma unroll
                for (int nt = 0; nt < 4; nt++) {
                    asm volatile(
                        "mma.sync.aligned.m16n8k16.row.col.f32.bf16.bf16.f32 "
                        "{%0,%1,%2,%3}, {%4,%5,%6,%7}, {%8,%9}, {%0,%1,%2,%3};"
                        : "+f"(acc[mt][nt][0]), "+f"(acc[mt][nt][1]),
                          "+f"(acc[mt][nt][2]), "+f"(acc[mt][nt][3])
                        : "r"(af[mt][0]), "r"(af[mt][1]),
                          "r"(af[mt][2]), "r"(af[mt][3]),
                          "r"(bf[nt][0]), "r"(bf[nt][1]));
                }
        }
    }

    // ---- epilogue ----
    __nv_bfloat16* Cb = Cg + (size_t)b * strideC;

    if (mode == 1) {
#pragma unroll
        for (int mt = 0; mt < 4; mt++) {
            int r0 = m0 + wm * 64 + mt * 16 + (lane >> 2);
#pragma unroll
            for (int nt = 0; nt < 4; nt++) {
                int c0 = n0 + wn * 32 + nt * 8 + (lane & 3) * 2;
                Cb[(size_t)c0 * 512 + r0]           = __float2bfloat16(acc[mt][nt][0]);
                Cb[(size_t)(c0 + 1) * 512 + r0]     = __float2bfloat16(acc[mt][nt][1]);
                Cb[(size_t)c0 * 512 + r0 + 8]       = __float2bfloat16(acc[mt][nt][2]);
                Cb[(size_t)(c0 + 1) * 512 + r0 + 8] = __float2bfloat16(acc[mt][nt][3]);
            }
        }
        // per-(nt, col-pair) sumsq over this warp's 8 m values, then over lanes
        float p0[4], p1[4];
#pragma unroll
        for (int nt = 0; nt < 4; nt++) {
            float s0 = 0.f, s1 = 0.f;
#pragma unroll
            for (int mt = 0; mt < 4; mt++) {
                s0 += acc[mt][nt][0] * acc[mt][nt][0] + acc[mt][nt][2] * acc[mt][nt][2];
                s1 += acc[mt][nt][1] * acc[mt][nt][1] + acc[mt][nt][3] * acc[mt][nt][3];
            }
#pragma unroll
            for (int o = 4; o < 32; o <<= 1) {
                s0 += __shfl_xor_sync(0xffffffffu, s0, o);
                s1 += __shfl_xor_sync(0xffffffffu, s1, o);
            }
            p0[nt] = s0; p1[nt] = s1;
        }
        __syncthreads();              // all warps past their last smem stage reads
        float* psum = (float*)sm;     // 128 floats, reuse staging smem
        if (wm == 0 && lane < 4) {
#pragma unroll
            for (int nt = 0; nt < 4; nt++) {
                int idx = wn * 32 + nt * 8 + lane * 2;
                psum[idx] = p0[nt]; psum[idx + 1] = p1[nt];
            }
        }
        __syncthreads();
        if (wm == 1 && lane < 4) {
#pragma unroll
            for (int nt = 0; nt < 4; nt++) {
                int idx = wn * 32 + nt * 8 + lane * 2;
                psum[idx] += p0[nt]; psum[idx + 1] += p1[nt];
            }
        }
        __syncthreads();
        if (tid < 128)
            colpart[((size_t)b * 4 + blockIdx.x) * DD + n0 + tid] = psum[tid];
    } else {
        const float* cp = colpart + (size_t)b * 4 * DD;
#pragma unroll
        for (int mt = 0; mt < 4; mt++) {
            int r0 = m0 + wm * 64 + mt * 16 + (lane >> 2);
            float cs0 = cp[r0] + cp[DD + r0] + cp[2 * DD + r0] + cp[3 * DD + r0];
            float cs1 = cp[r0 + 8] + cp[DD + r0 + 8] + cp[2 * DD + r0 + 8] + cp[3 * DD + r0 + 8];
            float sc0 = rsqrtf(fmaxf(cs0, EPSV));
            float sc1 = rsqrtf(fmaxf(cs1, EPSV));
#pragma unroll
            for (int nt = 0; nt < 4; nt++) {
                int c0 = n0 + wn * 32 + nt * 8 + (lane & 3) * 2;
                Cb[(size_t)c0 * 512 + r0]           = __float2bfloat16(acc[mt][nt][0] * sc0);
                Cb[(size_t)(c0 + 1) * 512 + r0]     = __float2bfloat16(acc[mt][nt][1] * sc0);
                Cb[(size_t)c0 * 512 + r0 + 8]       = __float2bfloat16(acc[mt][nt][2] * sc1);
                Cb[(size_t)(c0 + 1) * 512 + r0 + 8] = __float2bfloat16(acc[mt][nt][3] * sc1);
            }
        }
    }
}

// ---------------------------------------------------------------------------
// Perspective scores (128 thr, 1 row/block, warp w -> persps 5w..5w+4).
// 5-op inner: aw=a*w, hw=h*w; s1+=aw*aw, s2+=hw*hw, s3+=aw*hw.
// (w^2 factors out of all three sums, so the ratio is identical.)
// ---------------------------------------------------------------------------
__global__ void __launch_bounds__(128) k_persp(const float* __restrict__ inp_a,
                                               const float* __restrict__ W,
                                               float* __restrict__ out, int dup) {
    int row = blockIdx.x;
    int lane = threadIdx.x & 31;
    int w = threadIdx.x >> 5;

    const float4* a4p = (const float4*)(inp_a + (size_t)row * DD);
    const uint2* h2p = (const uint2*)(g_hmean_bf + (size_t)row * DD);
    float4 a[4], h[4];
#pragma unroll
    for (int i = 0; i < 4; i++) {
        a[i] = a4p[lane + 32 * i];
        uint2 hu = h2p[lane + 32 * i];
        float2 f0 = __bfloat1622float2(*(__nv_bfloat162*)&hu.x);
        float2 f1 = __bfloat1622float2(*(__nv_bfloat162*)&hu.y);
        h[i] = make_float4(f0.x, f0.y, f1.x, f1.y);
    }

#pragma unroll
    for (int pp = 0; pp < 5; pp++) {
        int p = w * 5 + pp;
        const float4* w4p = (const float4*)(W + (size_t)p * DD);
        float s1 = 0.f, s2 = 0.f, s3 = 0.f;
#pragma unroll
        for (int i = 0; i < 4; i++) {
            float4 wv = w4p[lane + 32 * i];
            float aw, hw;
            aw = a[i].x * wv.x; hw = h[i].x * wv.x; s1 += aw * aw; s2 += hw * hw; s3 += aw * hw;
            aw = a[i].y * wv.y; hw = h[i].y * wv.y; s1 += aw * aw; s2 += hw * hw; s3 += aw * hw;
            aw = a[i].z * wv.z; hw = h[i].z * wv.z; s1 += aw * aw; s2 += hw * hw; s3 += aw * hw;
            aw = a[i].w * wv.w; hw = h[i].w * wv.w; s1 += aw * aw; s2 += hw * hw; s3 += aw * hw;
        }
#pragma unroll
        for (int o = 16; o > 0; o >>= 1) {
            s1 += __shfl_xor_sync(0xffffffffu, s1, o);
            s2 += __shfl_xor_sync(0xffffffffu, s2, o);
            s3 += __shfl_xor_sync(0xffffffffu, s3, o);
        }
        if (lane == 0) {
            float v = s3 * rsqrtf(fmaxf(s1, EPSV)) * rsqrtf(fmaxf(s2, EPSV));
            out[(size_t)row * PP + p] = v;
            if (dup) out[(size_t)BB * TT * PP + (size_t)row * PP + p] = v;
        }
    }
}

// ---------------------------------------------------------------------------
extern "C" void kernel_launch(void* const* d_in, const int* in_sizes, int n_in,
                              void* d_out, int out_size) {
    const float* inp_a = (const float*)d_in[0];
    const float* inp_b = (const float*)d_in[1];
    const float* W     = (const float*)d_in[2];
    float* out = (float*)d_out;
    int dup = (out_size >= 2 * BB * TT * PP) ? 1 : 0;

    void *p_nbn_bf, *p_nbnT_bf, *p_nanT_bf, *p_alphaTb, *p_colpart, *p_hmean_bf;
    cudaGetSymbolAddress(&p_nbn_bf, g_nbn_bf);
    cudaGetSymbolAddress(&p_nbnT_bf, g_nbnT_bf);
    cudaGetSymbolAddress(&p_nanT_bf, g_nanT_bf);
    cudaGetSymbolAddress(&p_alphaTb, g_alphaTb);
    cudaGetSymbolAddress(&p_colpart, g_colpart);
    cudaGetSymbolAddress(&p_hmean_bf, g_hmean_bf);

    // 1) normalize + transpose -> bf16
    k_normT<<<dim3(TT / 16, BB, 2), 256>>>(inp_a, inp_b);

    // 2) GEMM1: alphaTb[e][d] = bf16( sum_t nbnT[d,t]*nanT[e,t] ) + colpart sumsq
    k_gemm_bf16<<<dim3(4, 4, BB), 256>>>(
        (const __nv_bfloat16*)p_nbnT_bf, TT, (size_t)DD * TT,
        (const __nv_bfloat16*)p_nanT_bf, TT, (size_t)DD * TT,
        (__nv_bfloat16*)p_alphaTb, (size_t)DD * DD,
        (float*)p_colpart, TT, 1);

    // 3) GEMM2: hmean_bf[t][e] = bf16( (sum_d alphaTb[e,d]*nbn[t,d]) * invcol[e] )
    k_gemm_bf16<<<dim3(4, 2, BB), 256>>>(
        (const __nv_bfloat16*)p_alphaTb, DD, (size_t)DD * DD,
        (const __nv_bfloat16*)p_nbn_bf, DD, (size_t)TT * DD,
        (__nv_bfloat16*)p_hmean_bf, (size_t)TT * DD,
        (float*)p_colpart, DD, 2);

    // 4) perspective scores
    k_persp<<<BB * TT, 128>>>(inp_a, W, out, dup);
}